// round 3
// baseline (speedup 1.0000x reference)
#include <cuda_runtime.h>
#include <cstdint>

// ===================== device scratch (static, no allocation) =====================
__device__ __align__(16) float g_emb[2048 * 256];     // [B*S, E]
__device__ __align__(16) float g_xw[2048 * 2048];     // [B*S, 4H] x@W_ih^T + b_ih + b_hh
__device__ __align__(16) float g_cat[2048 * 1024];    // [B*S, 2H]: [:512]=dec_out [512:]=context
__device__ __align__(16) float g_scores[16 * 128 * 128]; // [B,S,L] scores -> probs
__device__ __align__(16) float g_encT[16 * 512 * 128];   // [B,H,L]
__device__ __align__(16) float g_whhT[512 * 2048];       // W_hh transposed [K=512][4H=2048]
__device__ __align__(16) float g_hbuf[512 * 16];         // h state, layout [k][b]
__device__ __align__(16) float g_gates[16 * 2048];       // [b][4H]
__device__ __align__(16) float g_bcomb[2048];            // b_ih + b_hh
__device__ unsigned g_bar;
__device__ unsigned g_sense;

// ===================== helpers =====================
__device__ __forceinline__ void tf32_split(float x, uint32_t& hi, uint32_t& lo) {
    uint32_t h;
    asm("cvt.rna.tf32.f32 %0, %1;" : "=r"(h) : "f"(x));
    float r = x - __uint_as_float(h);
    uint32_t l;
    asm("cvt.rna.tf32.f32 %0, %1;" : "=r"(l) : "f"(r));
    hi = h; lo = l;
}

__device__ __forceinline__ void mma8(float* d, const uint32_t* a, const uint32_t* b) {
    asm volatile(
        "mma.sync.aligned.m16n8k8.row.col.f32.tf32.tf32.f32 "
        "{%0,%1,%2,%3}, {%4,%5,%6,%7}, {%8,%9}, {%0,%1,%2,%3};"
        : "+f"(d[0]), "+f"(d[1]), "+f"(d[2]), "+f"(d[3])
        : "r"(a[0]), "r"(a[1]), "r"(a[2]), "r"(a[3]), "r"(b[0]), "r"(b[1]));
}

__device__ __forceinline__ float sigm(float x) { return 1.f / (1.f + expf(-x)); }

// ===================== generic 3xTF32 GEMM: C = alpha*(A @ B^T) + bias =====================
// A [M,K] lda, B [N,K] ldb, C [M,N] ldc. grid (M/128, N/128, batch). 256 threads.
// smem: Ahi/Alo/Bhi/Blo each [32][136] u32 = 69632 bytes dynamic.
__global__ void __launch_bounds__(256) gemm3(
    const float* __restrict__ A, const float* __restrict__ B,
    float* __restrict__ C, const float* __restrict__ bias,
    int K, int lda, int ldb, int ldc,
    long long sA, long long sB, long long sC, float alpha)
{
    extern __shared__ uint32_t sm[];
    const int TL = 32 * 136;
    uint32_t* Ah = sm;
    uint32_t* Al = sm + TL;
    uint32_t* Bh = sm + 2 * TL;
    uint32_t* Bl = sm + 3 * TL;

    A += sA * blockIdx.z; B += sB * blockIdx.z; C += sC * blockIdx.z;
    const int m0 = blockIdx.x * 128, n0 = blockIdx.y * 128;
    const int tid = threadIdx.x, lane = tid & 31, warp = tid >> 5;
    const int wm = (warp & 1) * 64, wn = (warp >> 1) * 32;   // 2x4 warps, 64x32 warp tile
    const int gid = lane >> 2, tig = lane & 3;
    const int srow = tid >> 3, scol = (tid & 7) * 4;          // staging map

    float acc[4][4][4];
#pragma unroll
    for (int a = 0; a < 4; a++)
#pragma unroll
        for (int b = 0; b < 4; b++)
#pragma unroll
            for (int d = 0; d < 4; d++) acc[a][b][d] = 0.f;

    const int KT = K >> 5;
    float4 pa[4], pb[4];

    // prologue load
    {
        const float* Ap = A + (m0 + srow) * lda + scol;
        const float* Bp = B + (n0 + srow) * ldb + scol;
#pragma unroll
        for (int i = 0; i < 4; i++) {
            pa[i] = *(const float4*)(Ap + i * 32 * lda);
            pb[i] = *(const float4*)(Bp + i * 32 * ldb);
        }
    }

    for (int kt = 0; kt < KT; kt++) {
        // stage current tile (split hi/lo) into smem, k-major padded
#pragma unroll
        for (int i = 0; i < 4; i++) {
            int r = srow + 32 * i;
            float va[4] = {pa[i].x, pa[i].y, pa[i].z, pa[i].w};
            float vb[4] = {pb[i].x, pb[i].y, pb[i].z, pb[i].w};
#pragma unroll
            for (int j = 0; j < 4; j++) {
                uint32_t h, l;
                tf32_split(va[j], h, l);
                Ah[(scol + j) * 136 + r] = h;
                Al[(scol + j) * 136 + r] = l;
                tf32_split(vb[j], h, l);
                Bh[(scol + j) * 136 + r] = h;
                Bl[(scol + j) * 136 + r] = l;
            }
        }
        __syncthreads();

        if (kt + 1 < KT) {  // prefetch next (overlaps mma)
            const float* Ap = A + (m0 + srow) * lda + (kt + 1) * 32 + scol;
            const float* Bp = B + (n0 + srow) * ldb + (kt + 1) * 32 + scol;
#pragma unroll
            for (int i = 0; i < 4; i++) {
                pa[i] = *(const float4*)(Ap + i * 32 * lda);
                pb[i] = *(const float4*)(Bp + i * 32 * ldb);
            }
        }

#pragma unroll
        for (int k8 = 0; k8 < 4; k8++) {
            const int o0 = (k8 * 8 + tig) * 136;
            const int o4 = (k8 * 8 + tig + 4) * 136;
            uint32_t ah[4][4], al[4][4], bh[4][2], bl[4][2];
#pragma unroll
            for (int mf = 0; mf < 4; mf++) {
                int r = wm + mf * 16 + gid;
                ah[mf][0] = Ah[o0 + r]; ah[mf][1] = Ah[o0 + r + 8];
                ah[mf][2] = Ah[o4 + r]; ah[mf][3] = Ah[o4 + r + 8];
                al[mf][0] = Al[o0 + r]; al[mf][1] = Al[o0 + r + 8];
                al[mf][2] = Al[o4 + r]; al[mf][3] = Al[o4 + r + 8];
            }
#pragma unroll
            for (int nf = 0; nf < 4; nf++) {
                int c = wn + nf * 8 + gid;
                bh[nf][0] = Bh[o0 + c]; bh[nf][1] = Bh[o4 + c];
                bl[nf][0] = Bl[o0 + c]; bl[nf][1] = Bl[o4 + c];
            }
#pragma unroll
            for (int mf = 0; mf < 4; mf++)
#pragma unroll
                for (int nf = 0; nf < 4; nf++) {
                    mma8(acc[mf][nf], ah[mf], bh[nf]);
                    mma8(acc[mf][nf], ah[mf], bl[nf]);
                    mma8(acc[mf][nf], al[mf], bh[nf]);
                }
        }
        __syncthreads();
    }

    // epilogue
#pragma unroll
    for (int mf = 0; mf < 4; mf++) {
        int r = m0 + wm + mf * 16 + gid;
#pragma unroll
        for (int nf = 0; nf < 4; nf++) {
            int c = n0 + wn + nf * 8 + 2 * tig;
            float b0 = bias ? bias[c] : 0.f;
            float b1 = bias ? bias[c + 1] : 0.f;
            C[r * ldc + c]           = alpha * acc[mf][nf][0] + b0;
            C[r * ldc + c + 1]       = alpha * acc[mf][nf][1] + b1;
            C[(r + 8) * ldc + c]     = alpha * acc[mf][nf][2] + b0;
            C[(r + 8) * ldc + c + 1] = alpha * acc[mf][nf][3] + b1;
        }
    }
}

// ===================== small kernels =====================
__global__ void k_prep(const float* __restrict__ bih, const float* __restrict__ bhh) {
    int i = blockIdx.x * 256 + threadIdx.x;
    if (i < 2048) g_bcomb[i] = bih[i] + bhh[i];
    if (i < 8192) g_hbuf[i] = 0.f;
    if (i == 0) { g_bar = 0; g_sense = 0; }
}

__global__ void k_gather(const int* __restrict__ y, const float* __restrict__ tab) {
    int i = blockIdx.x * 256 + threadIdx.x;  // 2048*64 float4
    if (i < 2048 * 64) {
        int bs = i >> 6, e = i & 63;
        ((float4*)g_emb)[i] = ((const float4*)(tab + (long long)y[bs] * 256))[e];
    }
}

// in [z][R][C] -> out [z][C][R]
__global__ void k_transpose(const float* __restrict__ in, float* __restrict__ out, int R, int C) {
    __shared__ float t[32][33];
    in += (long long)blockIdx.z * R * C;
    out += (long long)blockIdx.z * R * C;
    int c0 = blockIdx.x * 32, r0 = blockIdx.y * 32;
    int x = threadIdx.x, y = threadIdx.y;
#pragma unroll
    for (int i = 0; i < 32; i += 8)
        if (r0 + y + i < R && c0 + x < C) t[y + i][x] = in[(r0 + y + i) * C + c0 + x];
    __syncthreads();
#pragma unroll
    for (int i = 0; i < 32; i += 8)
        if (c0 + y + i < C && r0 + x < R) out[(c0 + y + i) * R + r0 + x] = t[x][y + i];
}

// mask read as 32-bit words: nonzero => valid. Works for int32/float32/bf16x2/uint8
// materializations of a "true" boolean (any all-ones encoding is a nonzero word).
__global__ void k_softmax(const uint32_t* __restrict__ mask) {
    int w = (blockIdx.x * blockDim.x + threadIdx.x) >> 5;  // row 0..2047
    int lane = threadIdx.x & 31;
    if (w >= 2048) return;
    int b = w >> 7;
    float* row = g_scores + w * 128;
    const uint32_t* m = mask + b * 128;
    float v[4];
    float mx = -1e30f;
#pragma unroll
    for (int i = 0; i < 4; i++) {
        int l = lane + 32 * i;
        v[i] = (m[l] != 0u) ? row[l] : -1e9f;
        mx = fmaxf(mx, v[i]);
    }
#pragma unroll
    for (int o = 16; o > 0; o >>= 1) mx = fmaxf(mx, __shfl_xor_sync(0xffffffffu, mx, o));
    float s = 0.f;
#pragma unroll
    for (int i = 0; i < 4; i++) { v[i] = expf(v[i] - mx); s += v[i]; }
#pragma unroll
    for (int o = 16; o > 0; o >>= 1) s += __shfl_xor_sync(0xffffffffu, s, o);
    float inv = 1.f / s;
#pragma unroll
    for (int i = 0; i < 4; i++) row[lane + 32 * i] = v[i] * inv;
}

// ===================== persistent LSTM =====================
__device__ __forceinline__ void gridbar(unsigned target) {
    __syncthreads();
    if (threadIdx.x == 0) {
        __threadfence();
        unsigned v = atomicAdd(&g_bar, 1);
        if (v == 127u) {
            g_bar = 0;
            __threadfence();
            atomicAdd(&g_sense, 1);
        }
        while (*(volatile unsigned*)&g_sense < target) __nanosleep(64);
        __threadfence();
    }
    __syncthreads();
}

__global__ void __launch_bounds__(256) lstm_kernel(const float* __restrict__ xw) {
    extern __shared__ float smf[];
    float* h_sm = smf;            // [512][16]  h_sm[k*16+b]
    float* red = smf + 512 * 16;  // [16ks][16j][16b]

    const int tid = threadIdx.x, bk = blockIdx.x;
    const int ks = tid >> 4;
    const int bg = (tid >> 2) & 3;
    const int jg = tid & 3;
    const int j0 = bk * 16 + jg * 4;
    const int b0 = bg * 4;
    const int rj = tid >> 4, rb = tid & 15;  // reduce mapping

    const int p = bk * 256 + tid;            // phase-2 pair
    const int pb = p >> 9, pu = p & 511;
    float creg = 0.f;
    unsigned bt = 0;

    for (int t = 0; t < 128; t++) {
#pragma unroll
        for (int i = tid; i < 8192; i += 256) h_sm[i] = g_hbuf[i];
        __syncthreads();

        float a[4][4];
#pragma unroll
        for (int jj = 0; jj < 4; jj++)
#pragma unroll
            for (int bb = 0; bb < 4; bb++) a[jj][bb] = 0.f;

        const float* wp = g_whhT + (ks * 32) * 2048 + j0;
        const float* hp = h_sm + (ks * 32) * 16 + b0;
#pragma unroll 8
        for (int k = 0; k < 32; k++) {
            float4 wv = *(const float4*)wp;
            float4 hv = *(const float4*)hp;
            wp += 2048; hp += 16;
            float wa[4] = {wv.x, wv.y, wv.z, wv.w};
            float ha[4] = {hv.x, hv.y, hv.z, hv.w};
#pragma unroll
            for (int jj = 0; jj < 4; jj++)
#pragma unroll
                for (int bb = 0; bb < 4; bb++) a[jj][bb] = fmaf(wa[jj], ha[bb], a[jj][bb]);
        }
#pragma unroll
        for (int jj = 0; jj < 4; jj++)
#pragma unroll
            for (int bb = 0; bb < 4; bb++)
                red[ks * 256 + (jg * 4 + jj) * 16 + (bg * 4 + bb)] = a[jj][bb];
        __syncthreads();

        float s = 0.f;
#pragma unroll
        for (int q = 0; q < 16; q++) s += red[q * 256 + rj * 16 + rb];
        s += xw[(rb * 128 + t) * 2048 + bk * 16 + rj];
        g_gates[rb * 2048 + bk * 16 + rj] = s;

        gridbar(++bt);

        if (bk < 32) {
            const float* gr = g_gates + pb * 2048;
            float gi = gr[pu], gf = gr[512 + pu], gg = gr[1024 + pu], go = gr[1536 + pu];
            creg = sigm(gf) * creg + sigm(gi) * tanhf(gg);
            float h = sigm(go) * tanhf(creg);
            g_hbuf[pu * 16 + pb] = h;
            g_cat[(pb * 128 + t) * 1024 + pu] = h;
        }
        gridbar(++bt);
    }
}

// ===================== host launcher =====================
extern "C" void kernel_launch(void* const* d_in, const int* in_sizes, int n_in,
                              void* d_out, int out_size) {
    const int* y = (const int*)d_in[0];
    const float* tab = (const float*)d_in[1];
    const float* Wih = (const float*)d_in[2];
    const float* Whh = (const float*)d_in[3];
    const float* bih = (const float*)d_in[4];
    const float* bhh = (const float*)d_in[5];
    const float* enc = (const float*)d_in[6];
    const uint32_t* mask = (const uint32_t*)d_in[7];
    const float* Wout = (const float*)d_in[8];
    const float* bout = (const float*)d_in[9];
    float* out = (float*)d_out;

    float *p_emb, *p_xw, *p_cat, *p_scores, *p_encT, *p_whhT, *p_bcomb;
    cudaGetSymbolAddress((void**)&p_emb, g_emb);
    cudaGetSymbolAddress((void**)&p_xw, g_xw);
    cudaGetSymbolAddress((void**)&p_cat, g_cat);
    cudaGetSymbolAddress((void**)&p_scores, g_scores);
    cudaGetSymbolAddress((void**)&p_encT, g_encT);
    cudaGetSymbolAddress((void**)&p_whhT, g_whhT);
    cudaGetSymbolAddress((void**)&p_bcomb, g_bcomb);

    cudaFuncSetAttribute(gemm3, cudaFuncAttributeMaxDynamicSharedMemorySize, 69632);
    cudaFuncSetAttribute(lstm_kernel, cudaFuncAttributeMaxDynamicSharedMemorySize, 49152);

    k_prep<<<32, 256>>>(bih, bhh);
    k_transpose<<<dim3(16, 64, 1), dim3(32, 8)>>>(Whh, p_whhT, 2048, 512);
    k_gather<<<512, 256>>>(y, tab);
    // xw = emb @ W_ih^T + (b_ih + b_hh)
    gemm3<<<dim3(16, 16, 1), 256, 69632>>>(p_emb, Wih, p_xw, p_bcomb,
                                           256, 256, 256, 2048, 0, 0, 0, 1.f);
    k_transpose<<<dim3(16, 4, 16), dim3(32, 8)>>>(enc, p_encT, 128, 512);
    lstm_kernel<<<128, 256, 49152>>>(p_xw);
    // scores = dec @ enc^T / sqrt(H)
    gemm3<<<dim3(1, 1, 16), 256, 69632>>>(p_cat, enc, p_scores, nullptr,
                                          512, 1024, 512, 128,
                                          131072LL, 65536LL, 16384LL,
                                          0.044194173824159216f);
    k_softmax<<<256, 256>>>(mask);
    // context = probs @ enc  (via encT as B[N=H,K=L])
    gemm3<<<dim3(1, 4, 16), 256, 69632>>>(p_scores, p_encT, p_cat + 512, nullptr,
                                          128, 128, 128, 1024,
                                          16384LL, 65536LL, 131072LL, 1.f);
    // logits = cat @ W_out^T + b_out
    gemm3<<<dim3(16, 250, 1), 256, 69632>>>(p_cat, Wout, out, bout,
                                            1024, 1024, 1024, 32000, 0, 0, 0, 1.f);
}

// round 4
// speedup vs baseline: 1.5110x; 1.5110x over previous
#include <cuda_runtime.h>
#include <cuda_bf16.h>
#include <cstdint>

// ===================== device scratch (static, no allocation) =====================
__device__ __align__(16) float g_emb[2048 * 256];     // [B*S, E]
__device__ __align__(16) float g_xw[2048 * 2048];     // [B*S, 4H] x@W_ih^T + b_ih + b_hh
__device__ __align__(16) float g_cat[2048 * 1024];    // [B*S, 2H]: [:512]=dec_out [512:]=context
__device__ __align__(16) float g_scores[16 * 128 * 128]; // [B,S,L] scores -> probs
__device__ __align__(16) float g_encT[16 * 512 * 128];   // [B,H,L]
__device__ __align__(16) float g_whhT[512 * 2048];       // W_hh transposed [K=512][4H=2048]
__device__ __align__(16) float g_hbuf[512 * 16];         // h state, layout [k][b]
__device__ __align__(16) float g_gates[16 * 2048];       // [b][4H]
__device__ __align__(16) float g_bcomb[2048];            // b_ih + b_hh
__device__ unsigned g_bar;
__device__ unsigned g_sense;

// ===================== helpers =====================
__device__ __forceinline__ float sigm(float x) { return 1.f / (1.f + expf(-x)); }

__device__ __forceinline__ void mma16(float* d, const uint32_t* a, const uint32_t* b) {
    asm volatile(
        "mma.sync.aligned.m16n8k16.row.col.f32.bf16.bf16.f32 "
        "{%0,%1,%2,%3}, {%4,%5,%6,%7}, {%8,%9}, {%0,%1,%2,%3};"
        : "+f"(d[0]), "+f"(d[1]), "+f"(d[2]), "+f"(d[3])
        : "r"(a[0]), "r"(a[1]), "r"(a[2]), "r"(a[3]), "r"(b[0]), "r"(b[1]));
}

// ===================== split-bf16 3-term GEMM: C = alpha*(A @ B^T) + bias =====================
// A [M,K] lda, B [N,K] ldb, C [M,N] ldc. grid (M/128, N/128, batch). 512 threads.
// Error model: A = Ah + Al (bf16 split, ~16 mantissa bits); C ~= AhBh + AhBl + AlBh.
// smem: Ah/Al/Bh/Bl each [128][36] bf16 = 9216 B, total 36864 B.
#define GPAD 36
__global__ void __launch_bounds__(512, 1) gemmb(
    const float* __restrict__ A, const float* __restrict__ B,
    float* __restrict__ C, const float* __restrict__ bias,
    int K, int lda, int ldb, int ldc,
    long long sA, long long sB, long long sC, float alpha)
{
    extern __shared__ __nv_bfloat16 sm[];
    const int TL = 128 * GPAD;
    __nv_bfloat16* Ah = sm;
    __nv_bfloat16* Al = sm + TL;
    __nv_bfloat16* Bh = sm + 2 * TL;
    __nv_bfloat16* Bl = sm + 3 * TL;

    A += sA * blockIdx.z; B += sB * blockIdx.z; C += sC * blockIdx.z;
    const int m0 = blockIdx.x * 128, n0 = blockIdx.y * 128;
    const int tid = threadIdx.x, lane = tid & 31, warp = tid >> 5;
    const int wm = (warp & 3) * 32, wn = (warp >> 2) * 32;   // 4x4 warps, 32x32 warp tile
    const int gid = lane >> 2, tig = lane & 3;
    const int srow = tid >> 2, sc0 = (tid & 3) * 8;           // staging: 8 floats/thread

    float acc[2][4][4];
#pragma unroll
    for (int a = 0; a < 2; a++)
#pragma unroll
        for (int b = 0; b < 4; b++)
#pragma unroll
            for (int d = 0; d < 4; d++) acc[a][b][d] = 0.f;

    const int KT = K >> 5;
    float4 pa[2], pb[2];

    // prologue load
    {
        const float* Ap = A + (m0 + srow) * lda + sc0;
        const float* Bp = B + (n0 + srow) * ldb + sc0;
        pa[0] = *(const float4*)Ap;       pa[1] = *(const float4*)(Ap + 4);
        pb[0] = *(const float4*)Bp;       pb[1] = *(const float4*)(Bp + 4);
    }

    for (int kt = 0; kt < KT; kt++) {
        // stage (split hi/lo) into smem, [row][k] padded
        {
            float va[8] = {pa[0].x, pa[0].y, pa[0].z, pa[0].w, pa[1].x, pa[1].y, pa[1].z, pa[1].w};
            float vb[8] = {pb[0].x, pb[0].y, pb[0].z, pb[0].w, pb[1].x, pb[1].y, pb[1].z, pb[1].w};
            const int base = srow * GPAD + sc0;
#pragma unroll
            for (int j = 0; j < 8; j += 2) {
                __nv_bfloat16 h0 = __float2bfloat16(va[j]);
                __nv_bfloat16 h1 = __float2bfloat16(va[j + 1]);
                __nv_bfloat16 l0 = __float2bfloat16(va[j] - __bfloat162float(h0));
                __nv_bfloat16 l1 = __float2bfloat16(va[j + 1] - __bfloat162float(h1));
                *(__nv_bfloat162*)&Ah[base + j] = __nv_bfloat162(h0, h1);
                *(__nv_bfloat162*)&Al[base + j] = __nv_bfloat162(l0, l1);
                h0 = __float2bfloat16(vb[j]);
                h1 = __float2bfloat16(vb[j + 1]);
                l0 = __float2bfloat16(vb[j] - __bfloat162float(h0));
                l1 = __float2bfloat16(vb[j + 1] - __bfloat162float(h1));
                *(__nv_bfloat162*)&Bh[base + j] = __nv_bfloat162(h0, h1);
                *(__nv_bfloat162*)&Bl[base + j] = __nv_bfloat162(l0, l1);
            }
        }
        __syncthreads();

        if (kt + 1 < KT) {  // prefetch next tile into registers (overlaps mma)
            const float* Ap = A + (m0 + srow) * lda + (kt + 1) * 32 + sc0;
            const float* Bp = B + (n0 + srow) * ldb + (kt + 1) * 32 + sc0;
            pa[0] = *(const float4*)Ap;   pa[1] = *(const float4*)(Ap + 4);
            pb[0] = *(const float4*)Bp;   pb[1] = *(const float4*)(Bp + 4);
        }

#pragma unroll
        for (int k16 = 0; k16 < 2; k16++) {
            const int kb = k16 * 16 + tig * 2;
            uint32_t ah[2][4], al[2][4], bh[4][2], bl[4][2];
#pragma unroll
            for (int mf = 0; mf < 2; mf++) {
                const int r = wm + mf * 16 + gid;
                ah[mf][0] = *(const uint32_t*)&Ah[r * GPAD + kb];
                ah[mf][1] = *(const uint32_t*)&Ah[(r + 8) * GPAD + kb];
                ah[mf][2] = *(const uint32_t*)&Ah[r * GPAD + kb + 8];
                ah[mf][3] = *(const uint32_t*)&Ah[(r + 8) * GPAD + kb + 8];
                al[mf][0] = *(const uint32_t*)&Al[r * GPAD + kb];
                al[mf][1] = *(const uint32_t*)&Al[(r + 8) * GPAD + kb];
                al[mf][2] = *(const uint32_t*)&Al[r * GPAD + kb + 8];
                al[mf][3] = *(const uint32_t*)&Al[(r + 8) * GPAD + kb + 8];
            }
#pragma unroll
            for (int nf = 0; nf < 4; nf++) {
                const int c = wn + nf * 8 + gid;
                bh[nf][0] = *(const uint32_t*)&Bh[c * GPAD + kb];
                bh[nf][1] = *(const uint32_t*)&Bh[c * GPAD + kb + 8];
                bl[nf][0] = *(const uint32_t*)&Bl[c * GPAD + kb];
                bl[nf][1] = *(const uint32_t*)&Bl[c * GPAD + kb + 8];
            }
#pragma unroll
            for (int mf = 0; mf < 2; mf++)
#pragma unroll
                for (int nf = 0; nf < 4; nf++) {
                    mma16(acc[mf][nf], ah[mf], bh[nf]);
                    mma16(acc[mf][nf], ah[mf], bl[nf]);
                    mma16(acc[mf][nf], al[mf], bh[nf]);
                }
        }
        __syncthreads();
    }

    // epilogue
#pragma unroll
    for (int mf = 0; mf < 2; mf++) {
        const int r = m0 + wm + mf * 16 + gid;
#pragma unroll
        for (int nf = 0; nf < 4; nf++) {
            const int c = n0 + wn + nf * 8 + 2 * tig;
            float b0 = bias ? bias[c] : 0.f;
            float b1 = bias ? bias[c + 1] : 0.f;
            C[r * ldc + c]           = alpha * acc[mf][nf][0] + b0;
            C[r * ldc + c + 1]       = alpha * acc[mf][nf][1] + b1;
            C[(r + 8) * ldc + c]     = alpha * acc[mf][nf][2] + b0;
            C[(r + 8) * ldc + c + 1] = alpha * acc[mf][nf][3] + b1;
        }
    }
}

// ===================== small kernels =====================
__global__ void k_prep(const float* __restrict__ bih, const float* __restrict__ bhh) {
    int i = blockIdx.x * 256 + threadIdx.x;
    if (i < 2048) g_bcomb[i] = bih[i] + bhh[i];
    if (i < 8192) g_hbuf[i] = 0.f;
    if (i == 0) { g_bar = 0; g_sense = 0; }
}

__global__ void k_gather(const int* __restrict__ y, const float* __restrict__ tab) {
    int i = blockIdx.x * 256 + threadIdx.x;  // 2048*64 float4
    if (i < 2048 * 64) {
        int bs = i >> 6, e = i & 63;
        ((float4*)g_emb)[i] = ((const float4*)(tab + (long long)y[bs] * 256))[e];
    }
}

// in [z][R][C] -> out [z][C][R]
__global__ void k_transpose(const float* __restrict__ in, float* __restrict__ out, int R, int C) {
    __shared__ float t[32][33];
    in += (long long)blockIdx.z * R * C;
    out += (long long)blockIdx.z * R * C;
    int c0 = blockIdx.x * 32, r0 = blockIdx.y * 32;
    int x = threadIdx.x, y = threadIdx.y;
#pragma unroll
    for (int i = 0; i < 32; i += 8)
        if (r0 + y + i < R && c0 + x < C) t[y + i][x] = in[(r0 + y + i) * C + c0 + x];
    __syncthreads();
#pragma unroll
    for (int i = 0; i < 32; i += 8)
        if (c0 + y + i < C && r0 + x < R) out[(c0 + y + i) * R + r0 + x] = t[x][y + i];
}

// mask read as 32-bit words: nonzero => valid (robust to int32/f32/u8 materialization)
__global__ void k_softmax(const uint32_t* __restrict__ mask) {
    int w = (blockIdx.x * blockDim.x + threadIdx.x) >> 5;  // row 0..2047
    int lane = threadIdx.x & 31;
    if (w >= 2048) return;
    int b = w >> 7;
    float* row = g_scores + w * 128;
    const uint32_t* m = mask + b * 128;
    float v[4];
    float mx = -1e30f;
#pragma unroll
    for (int i = 0; i < 4; i++) {
        int l = lane + 32 * i;
        v[i] = (m[l] != 0u) ? row[l] : -1e9f;
        mx = fmaxf(mx, v[i]);
    }
#pragma unroll
    for (int o = 16; o > 0; o >>= 1) mx = fmaxf(mx, __shfl_xor_sync(0xffffffffu, mx, o));
    float s = 0.f;
#pragma unroll
    for (int i = 0; i < 4; i++) { v[i] = expf(v[i] - mx); s += v[i]; }
#pragma unroll
    for (int o = 16; o > 0; o >>= 1) s += __shfl_xor_sync(0xffffffffu, s, o);
    float inv = 1.f / s;
#pragma unroll
    for (int i = 0; i < 4; i++) row[lane + 32 * i] = v[i] * inv;
}

// ===================== persistent LSTM =====================
__device__ __forceinline__ void gridbar(unsigned target) {
    __syncthreads();
    if (threadIdx.x == 0) {
        __threadfence();
        unsigned v = atomicAdd(&g_bar, 1);
        if (v == 127u) {
            g_bar = 0;
            __threadfence();
            atomicAdd(&g_sense, 1);
        }
        while (*(volatile unsigned*)&g_sense < target) __nanosleep(64);
        __threadfence();
    }
    __syncthreads();
}

__global__ void __launch_bounds__(256) lstm_kernel(const float* __restrict__ xw) {
    extern __shared__ float smf[];
    float* h_sm = smf;            // [512][16]  h_sm[k*16+b]
    float* red = smf + 512 * 16;  // [16ks][16j][16b]

    const int tid = threadIdx.x, bk = blockIdx.x;
    const int ks = tid >> 4;
    const int bg = (tid >> 2) & 3;
    const int jg = tid & 3;
    const int j0 = bk * 16 + jg * 4;
    const int b0 = bg * 4;
    const int rj = tid >> 4, rb = tid & 15;  // reduce mapping

    const int p = bk * 256 + tid;            // phase-2 pair
    const int pb = p >> 9, pu = p & 511;
    float creg = 0.f;
    unsigned bt = 0;

    for (int t = 0; t < 128; t++) {
#pragma unroll
        for (int i = tid; i < 8192; i += 256) h_sm[i] = g_hbuf[i];
        __syncthreads();

        float a[4][4];
#pragma unroll
        for (int jj = 0; jj < 4; jj++)
#pragma unroll
            for (int bb = 0; bb < 4; bb++) a[jj][bb] = 0.f;

        const float* wp = g_whhT + (ks * 32) * 2048 + j0;
        const float* hp = h_sm + (ks * 32) * 16 + b0;
#pragma unroll 8
        for (int k = 0; k < 32; k++) {
            float4 wv = *(const float4*)wp;
            float4 hv = *(const float4*)hp;
            wp += 2048; hp += 16;
            float wa[4] = {wv.x, wv.y, wv.z, wv.w};
            float ha[4] = {hv.x, hv.y, hv.z, hv.w};
#pragma unroll
            for (int jj = 0; jj < 4; jj++)
#pragma unroll
                for (int bb = 0; bb < 4; bb++) a[jj][bb] = fmaf(wa[jj], ha[bb], a[jj][bb]);
        }
#pragma unroll
        for (int jj = 0; jj < 4; jj++)
#pragma unroll
            for (int bb = 0; bb < 4; bb++)
                red[ks * 256 + (jg * 4 + jj) * 16 + (bg * 4 + bb)] = a[jj][bb];
        __syncthreads();

        float s = 0.f;
#pragma unroll
        for (int q = 0; q < 16; q++) s += red[q * 256 + rj * 16 + rb];
        s += xw[(rb * 128 + t) * 2048 + bk * 16 + rj];
        g_gates[rb * 2048 + bk * 16 + rj] = s;

        gridbar(++bt);

        if (bk < 32) {
            const float* gr = g_gates + pb * 2048;
            float gi = gr[pu], gf = gr[512 + pu], gg = gr[1024 + pu], go = gr[1536 + pu];
            creg = sigm(gf) * creg + sigm(gi) * tanhf(gg);
            float h = sigm(go) * tanhf(creg);
            g_hbuf[pu * 16 + pb] = h;
            g_cat[(pb * 128 + t) * 1024 + pu] = h;
        }
        gridbar(++bt);
    }
}

// ===================== host launcher =====================
extern "C" void kernel_launch(void* const* d_in, const int* in_sizes, int n_in,
                              void* d_out, int out_size) {
    const int* y = (const int*)d_in[0];
    const float* tab = (const float*)d_in[1];
    const float* Wih = (const float*)d_in[2];
    const float* Whh = (const float*)d_in[3];
    const float* bih = (const float*)d_in[4];
    const float* bhh = (const float*)d_in[5];
    const float* enc = (const float*)d_in[6];
    const uint32_t* mask = (const uint32_t*)d_in[7];
    const float* Wout = (const float*)d_in[8];
    const float* bout = (const float*)d_in[9];
    float* out = (float*)d_out;

    float *p_emb, *p_xw, *p_cat, *p_scores, *p_encT, *p_whhT, *p_bcomb;
    cudaGetSymbolAddress((void**)&p_emb, g_emb);
    cudaGetSymbolAddress((void**)&p_xw, g_xw);
    cudaGetSymbolAddress((void**)&p_cat, g_cat);
    cudaGetSymbolAddress((void**)&p_scores, g_scores);
    cudaGetSymbolAddress((void**)&p_encT, g_encT);
    cudaGetSymbolAddress((void**)&p_whhT, g_whhT);
    cudaGetSymbolAddress((void**)&p_bcomb, g_bcomb);

    cudaFuncSetAttribute(lstm_kernel, cudaFuncAttributeMaxDynamicSharedMemorySize, 49152);

    const int GSM = 4 * 128 * GPAD * 2;  // 36864 bytes

    k_prep<<<32, 256>>>(bih, bhh);
    k_transpose<<<dim3(16, 64, 1), dim3(32, 8)>>>(Whh, p_whhT, 2048, 512);
    k_gather<<<512, 256>>>(y, tab);
    // xw = emb @ W_ih^T + (b_ih + b_hh)
    gemmb<<<dim3(16, 16, 1), 512, GSM>>>(p_emb, Wih, p_xw, p_bcomb,
                                         256, 256, 256, 2048, 0, 0, 0, 1.f);
    k_transpose<<<dim3(16, 4, 16), dim3(32, 8)>>>(enc, p_encT, 128, 512);
    lstm_kernel<<<128, 256, 49152>>>(p_xw);
    // scores = dec @ enc^T / sqrt(H)
    gemmb<<<dim3(1, 1, 16), 512, GSM>>>(p_cat, enc, p_scores, nullptr,
                                        512, 1024, 512, 128,
                                        131072LL, 65536LL, 16384LL,
                                        0.044194173824159216f);
    k_softmax<<<256, 256>>>(mask);
    // context = probs @ enc  (via encT as B[N=H,K=L])
    gemmb<<<dim3(1, 4, 16), 512, GSM>>>(p_scores, p_encT, p_cat + 512, nullptr,
                                        128, 128, 128, 1024,
                                        16384LL, 65536LL, 131072LL, 1.f);
    // logits = cat @ W_out^T + b_out
    gemmb<<<dim3(16, 250, 1), 512, GSM>>>(p_cat, Wout, out, bout,
                                          1024, 1024, 1024, 32000, 0, 0, 0, 1.f);
}

// round 5
// speedup vs baseline: 1.8526x; 1.2261x over previous
#include <cuda_runtime.h>
#include <cuda_bf16.h>
#include <cstdint>

// ===================== device scratch (static, no allocation) =====================
__device__ __align__(16) float g_emb[2048 * 256];        // [B*S, E]
__device__ __align__(16) float g_xw[2048 * 2048];        // [B*S, 4H]
__device__ __align__(16) float g_cat[2048 * 1024];       // [B*S, 2H]
__device__ __align__(16) float g_scores[16 * 128 * 128]; // [B,S,L]
__device__ __align__(16) float g_encT[16 * 512 * 128];   // [B,H,L]
__device__ __align__(16) float g_whhT[512 * 2048];       // W_hh^T
__device__ __align__(16) float g_hbuf[512 * 16];
__device__ __align__(16) float g_gates[16 * 2048];
__device__ __align__(16) float g_bcomb[2048];
__device__ unsigned g_bar;
__device__ unsigned g_sense;

// pre-split bf16 hi/lo operand arrays
__device__ __align__(16) __nv_bfloat16 s_emb_h[2048 * 256],  s_emb_l[2048 * 256];
__device__ __align__(16) __nv_bfloat16 s_wih_h[2048 * 256],  s_wih_l[2048 * 256];
__device__ __align__(16) __nv_bfloat16 s_cat_h[2048 * 1024], s_cat_l[2048 * 1024];
__device__ __align__(16) __nv_bfloat16 s_wout_h[32000 * 1024], s_wout_l[32000 * 1024];
__device__ __align__(16) __nv_bfloat16 s_enc_h[16 * 128 * 512], s_enc_l[16 * 128 * 512];
__device__ __align__(16) __nv_bfloat16 s_encT_h[16 * 512 * 128], s_encT_l[16 * 512 * 128];
__device__ __align__(16) __nv_bfloat16 s_sc_h[16 * 128 * 128], s_sc_l[16 * 128 * 128];

// ===================== helpers =====================
__device__ __forceinline__ float sigm(float x) { return 1.f / (1.f + expf(-x)); }

__device__ __forceinline__ void mma16(float* d, const uint32_t* a, const uint32_t* b) {
    asm volatile(
        "mma.sync.aligned.m16n8k16.row.col.f32.bf16.bf16.f32 "
        "{%0,%1,%2,%3}, {%4,%5,%6,%7}, {%8,%9}, {%0,%1,%2,%3};"
        : "+f"(d[0]), "+f"(d[1]), "+f"(d[2]), "+f"(d[3])
        : "r"(a[0]), "r"(a[1]), "r"(a[2]), "r"(a[3]), "r"(b[0]), "r"(b[1]));
}

__device__ __forceinline__ void ldsm4(uint32_t& r0, uint32_t& r1, uint32_t& r2, uint32_t& r3,
                                      uint32_t addr) {
    asm volatile("ldmatrix.sync.aligned.m8n8.x4.shared.b16 {%0,%1,%2,%3}, [%4];"
                 : "=r"(r0), "=r"(r1), "=r"(r2), "=r"(r3) : "r"(addr));
}

__device__ __forceinline__ void cpasync16(uint32_t dst, const void* src) {
    asm volatile("cp.async.cg.shared.global [%0], [%1], 16;" :: "r"(dst), "l"(src));
}

// ===================== split-bf16 3-term GEMM (pre-split operands) =====================
// C = alpha * (A @ B^T) + bias; A,B given as hi/lo bf16 pairs, [M,K]/[N,K] k-major.
// Block tile 128x128, 256 threads (8 warps, 2x4, warp tile 64x32), cp.async 2-stage,
// ldmatrix fragment loads. K % 32 == 0 required.
#define PITCH 80                 // smem row pitch bytes (32 bf16 data + 16B pad)
#define MAT_B (128 * PITCH)      // 10240 B per matrix tile
#define STG_B (4 * MAT_B)        // 40960 B per stage

__global__ void __launch_bounds__(256, 2) gemmb(
    const __nv_bfloat16* __restrict__ Ahg, const __nv_bfloat16* __restrict__ Alg,
    const __nv_bfloat16* __restrict__ Bhg, const __nv_bfloat16* __restrict__ Blg,
    float* __restrict__ C, const float* __restrict__ bias,
    int K, int lda, int ldb, int ldc,
    long long sA, long long sB, long long sC, float alpha)
{
    extern __shared__ char smc[];
    const uint32_t sb = (uint32_t)__cvta_generic_to_shared(smc);

    Ahg += sA * blockIdx.z; Alg += sA * blockIdx.z;
    Bhg += sB * blockIdx.z; Blg += sB * blockIdx.z;
    C += sC * blockIdx.z;

    const int m0 = blockIdx.x * 128, n0 = blockIdx.y * 128;
    const int tid = threadIdx.x, lane = tid & 31, warp = tid >> 5;
    const int wm = (warp & 1) * 64, wn = (warp >> 1) * 32;
    const int gid = lane >> 2, tig = lane & 3;
    const int rsel = lane & 15, csel = (lane >> 4) * 16;

    const int KT = K >> 5;

    // cp.async mapping: chunk c (0..511 per matrix): row=c>>2, 16B-off=(c&3)*16
    const int lrow = tid >> 2, loff = tid & 3;

    float acc[4][4][4];
#pragma unroll
    for (int a = 0; a < 4; a++)
#pragma unroll
        for (int b = 0; b < 4; b++)
#pragma unroll
            for (int d = 0; d < 4; d++) acc[a][b][d] = 0.f;

#define LOAD_STAGE(KT_IDX, ST)                                                          \
    {                                                                                   \
        const int kofs = (KT_IDX) * 32 + loff * 8;                                      \
        const uint32_t db = sb + (ST) * STG_B + lrow * PITCH + loff * 16;               \
        cpasync16(db,                  Ahg + (long long)(m0 + lrow) * lda + kofs);      \
        cpasync16(db + 64 * PITCH,     Ahg + (long long)(m0 + lrow + 64) * lda + kofs); \
        cpasync16(db + MAT_B,          Alg + (long long)(m0 + lrow) * lda + kofs);      \
        cpasync16(db + MAT_B + 64 * PITCH, Alg + (long long)(m0 + lrow + 64) * lda + kofs); \
        cpasync16(db + 2 * MAT_B,      Bhg + (long long)(n0 + lrow) * ldb + kofs);      \
        cpasync16(db + 2 * MAT_B + 64 * PITCH, Bhg + (long long)(n0 + lrow + 64) * ldb + kofs); \
        cpasync16(db + 3 * MAT_B,      Blg + (long long)(n0 + lrow) * ldb + kofs);      \
        cpasync16(db + 3 * MAT_B + 64 * PITCH, Blg + (long long)(n0 + lrow + 64) * ldb + kofs); \
        asm volatile("cp.async.commit_group;");                                         \
    }

    LOAD_STAGE(0, 0);

    for (int kt = 0; kt < KT; kt++) {
        if (kt + 1 < KT) {
            LOAD_STAGE(kt + 1, (kt + 1) & 1);
            asm volatile("cp.async.wait_group 1;");
        } else {
            asm volatile("cp.async.wait_group 0;");
        }
        __syncthreads();

        const uint32_t base = sb + (kt & 1) * STG_B;
#pragma unroll
        for (int k16 = 0; k16 < 2; k16++) {
            const uint32_t kof = k16 * 32 + csel;
            uint32_t ah[4][4], al[4][4], bh[4][2], bl[4][2];
#pragma unroll
            for (int mf = 0; mf < 4; mf++) {
                const uint32_t ra = base + (wm + mf * 16 + rsel) * PITCH + kof;
                ldsm4(ah[mf][0], ah[mf][1], ah[mf][2], ah[mf][3], ra);
                ldsm4(al[mf][0], al[mf][1], al[mf][2], al[mf][3], ra + MAT_B);
            }
#pragma unroll
            for (int np = 0; np < 2; np++) {
                const uint32_t rb = base + 2 * MAT_B + (wn + np * 16 + rsel) * PITCH + kof;
                uint32_t t0, t1, t2, t3;
                ldsm4(t0, t1, t2, t3, rb);
                bh[2 * np][0] = t0; bh[2 * np][1] = t2;
                bh[2 * np + 1][0] = t1; bh[2 * np + 1][1] = t3;
                ldsm4(t0, t1, t2, t3, rb + MAT_B);
                bl[2 * np][0] = t0; bl[2 * np][1] = t2;
                bl[2 * np + 1][0] = t1; bl[2 * np + 1][1] = t3;
            }
#pragma unroll
            for (int mf = 0; mf < 4; mf++)
#pragma unroll
                for (int nf = 0; nf < 4; nf++) {
                    mma16(acc[mf][nf], ah[mf], bh[nf]);
                    mma16(acc[mf][nf], ah[mf], bl[nf]);
                    mma16(acc[mf][nf], al[mf], bh[nf]);
                }
        }
        __syncthreads();
    }

    // epilogue
#pragma unroll
    for (int mf = 0; mf < 4; mf++) {
        const int r = m0 + wm + mf * 16 + gid;
#pragma unroll
        for (int nf = 0; nf < 4; nf++) {
            const int c = n0 + wn + nf * 8 + 2 * tig;
            float b0 = bias ? bias[c] : 0.f;
            float b1 = bias ? bias[c + 1] : 0.f;
            float2 v0 = {alpha * acc[mf][nf][0] + b0, alpha * acc[mf][nf][1] + b1};
            float2 v1 = {alpha * acc[mf][nf][2] + b0, alpha * acc[mf][nf][3] + b1};
            *(float2*)&C[(long long)r * ldc + c] = v0;
            *(float2*)&C[(long long)(r + 8) * ldc + c] = v1;
        }
    }
}

// ===================== split kernel: float -> bf16 hi + bf16 lo =====================
__global__ void k_split(const float4* __restrict__ in, __nv_bfloat162* __restrict__ hi,
                        __nv_bfloat162* __restrict__ lo, int n4) {
    int i = blockIdx.x * 256 + threadIdx.x;
    if (i >= n4) return;
    float4 v = in[i];
    __nv_bfloat16 h0 = __float2bfloat16(v.x), h1 = __float2bfloat16(v.y);
    __nv_bfloat16 h2 = __float2bfloat16(v.z), h3 = __float2bfloat16(v.w);
    hi[2 * i]     = __nv_bfloat162(h0, h1);
    hi[2 * i + 1] = __nv_bfloat162(h2, h3);
    lo[2 * i]     = __nv_bfloat162(__float2bfloat16(v.x - __bfloat162float(h0)),
                                   __float2bfloat16(v.y - __bfloat162float(h1)));
    lo[2 * i + 1] = __nv_bfloat162(__float2bfloat16(v.z - __bfloat162float(h2)),
                                   __float2bfloat16(v.w - __bfloat162float(h3)));
}

// ===================== small kernels =====================
__global__ void k_prep(const float* __restrict__ bih, const float* __restrict__ bhh) {
    int i = blockIdx.x * 256 + threadIdx.x;
    if (i < 2048) g_bcomb[i] = bih[i] + bhh[i];
    if (i < 8192) g_hbuf[i] = 0.f;
    if (i == 0) { g_bar = 0; g_sense = 0; }
}

__global__ void k_gather(const int* __restrict__ y, const float* __restrict__ tab) {
    int i = blockIdx.x * 256 + threadIdx.x;
    if (i < 2048 * 64) {
        int bs = i >> 6, e = i & 63;
        ((float4*)g_emb)[i] = ((const float4*)(tab + (long long)y[bs] * 256))[e];
    }
}

__global__ void k_transpose(const float* __restrict__ in, float* __restrict__ out, int R, int C) {
    __shared__ float t[32][33];
    in += (long long)blockIdx.z * R * C;
    out += (long long)blockIdx.z * R * C;
    int c0 = blockIdx.x * 32, r0 = blockIdx.y * 32;
    int x = threadIdx.x, y = threadIdx.y;
#pragma unroll
    for (int i = 0; i < 32; i += 8)
        if (r0 + y + i < R && c0 + x < C) t[y + i][x] = in[(r0 + y + i) * C + c0 + x];
    __syncthreads();
#pragma unroll
    for (int i = 0; i < 32; i += 8)
        if (c0 + y + i < C && r0 + x < R) out[(c0 + y + i) * R + r0 + x] = t[x][y + i];
}

__global__ void k_softmax(const uint32_t* __restrict__ mask) {
    int w = (blockIdx.x * blockDim.x + threadIdx.x) >> 5;
    int lane = threadIdx.x & 31;
    if (w >= 2048) return;
    int b = w >> 7;
    float* row = g_scores + w * 128;
    const uint32_t* m = mask + b * 128;
    float v[4];
    float mx = -1e30f;
#pragma unroll
    for (int i = 0; i < 4; i++) {
        int l = lane + 32 * i;
        v[i] = (m[l] != 0u) ? row[l] : -1e9f;
        mx = fmaxf(mx, v[i]);
    }
#pragma unroll
    for (int o = 16; o > 0; o >>= 1) mx = fmaxf(mx, __shfl_xor_sync(0xffffffffu, mx, o));
    float s = 0.f;
#pragma unroll
    for (int i = 0; i < 4; i++) { v[i] = expf(v[i] - mx); s += v[i]; }
#pragma unroll
    for (int o = 16; o > 0; o >>= 1) s += __shfl_xor_sync(0xffffffffu, s, o);
    float inv = 1.f / s;
#pragma unroll
    for (int i = 0; i < 4; i++) row[lane + 32 * i] = v[i] * inv;
}

// ===================== persistent LSTM (unchanged) =====================
__device__ __forceinline__ void gridbar(unsigned target) {
    __syncthreads();
    if (threadIdx.x == 0) {
        __threadfence();
        unsigned v = atomicAdd(&g_bar, 1);
        if (v == 127u) {
            g_bar = 0;
            __threadfence();
            atomicAdd(&g_sense, 1);
        }
        while (*(volatile unsigned*)&g_sense < target) __nanosleep(64);
        __threadfence();
    }
    __syncthreads();
}

__global__ void __launch_bounds__(256) lstm_kernel(const float* __restrict__ xw) {
    extern __shared__ float smf[];
    float* h_sm = smf;
    float* red = smf + 512 * 16;

    const int tid = threadIdx.x, bk = blockIdx.x;
    const int ks = tid >> 4;
    const int bg = (tid >> 2) & 3;
    const int jg = tid & 3;
    const int j0 = bk * 16 + jg * 4;
    const int b0 = bg * 4;
    const int rj = tid >> 4, rb = tid & 15;

    const int p = bk * 256 + tid;
    const int pb = p >> 9, pu = p & 511;
    float creg = 0.f;
    unsigned bt = 0;

    for (int t = 0; t < 128; t++) {
#pragma unroll
        for (int i = tid; i < 8192; i += 256) h_sm[i] = g_hbuf[i];
        __syncthreads();

        float a[4][4];
#pragma unroll
        for (int jj = 0; jj < 4; jj++)
#pragma unroll
            for (int bb = 0; bb < 4; bb++) a[jj][bb] = 0.f;

        const float* wp = g_whhT + (ks * 32) * 2048 + j0;
        const float* hp = h_sm + (ks * 32) * 16 + b0;
#pragma unroll 8
        for (int k = 0; k < 32; k++) {
            float4 wv = *(const float4*)wp;
            float4 hv = *(const float4*)hp;
            wp += 2048; hp += 16;
            float wa[4] = {wv.x, wv.y, wv.z, wv.w};
            float ha[4] = {hv.x, hv.y, hv.z, hv.w};
#pragma unroll
            for (int jj = 0; jj < 4; jj++)
#pragma unroll
                for (int bb = 0; bb < 4; bb++) a[jj][bb] = fmaf(wa[jj], ha[bb], a[jj][bb]);
        }
#pragma unroll
        for (int jj = 0; jj < 4; jj++)
#pragma unroll
            for (int bb = 0; bb < 4; bb++)
                red[ks * 256 + (jg * 4 + jj) * 16 + (bg * 4 + bb)] = a[jj][bb];
        __syncthreads();

        float s = 0.f;
#pragma unroll
        for (int q = 0; q < 16; q++) s += red[q * 256 + rj * 16 + rb];
        s += xw[(rb * 128 + t) * 2048 + bk * 16 + rj];
        g_gates[rb * 2048 + bk * 16 + rj] = s;

        gridbar(++bt);

        if (bk < 32) {
            const float* gr = g_gates + pb * 2048;
            float gi = gr[pu], gf = gr[512 + pu], gg = gr[1024 + pu], go = gr[1536 + pu];
            creg = sigm(gf) * creg + sigm(gi) * tanhf(gg);
            float h = sigm(go) * tanhf(creg);
            g_hbuf[pu * 16 + pb] = h;
            g_cat[(pb * 128 + t) * 1024 + pu] = h;
        }
        gridbar(++bt);
    }
}

// ===================== host launcher =====================
extern "C" void kernel_launch(void* const* d_in, const int* in_sizes, int n_in,
                              void* d_out, int out_size) {
    const int* y = (const int*)d_in[0];
    const float* tab = (const float*)d_in[1];
    const float* Wih = (const float*)d_in[2];
    const float* Whh = (const float*)d_in[3];
    const float* bih = (const float*)d_in[4];
    const float* bhh = (const float*)d_in[5];
    const float* enc = (const float*)d_in[6];
    const uint32_t* mask = (const uint32_t*)d_in[7];
    const float* Wout = (const float*)d_in[8];
    const float* bout = (const float*)d_in[9];
    float* out = (float*)d_out;

    float *p_emb, *p_xw, *p_cat, *p_scores, *p_encT, *p_whhT, *p_bcomb;
    cudaGetSymbolAddress((void**)&p_emb, g_emb);
    cudaGetSymbolAddress((void**)&p_xw, g_xw);
    cudaGetSymbolAddress((void**)&p_cat, g_cat);
    cudaGetSymbolAddress((void**)&p_scores, g_scores);
    cudaGetSymbolAddress((void**)&p_encT, g_encT);
    cudaGetSymbolAddress((void**)&p_whhT, g_whhT);
    cudaGetSymbolAddress((void**)&p_bcomb, g_bcomb);

    __nv_bfloat16 *e_h, *e_l, *wi_h, *wi_l, *c_h, *c_l, *wo_h, *wo_l;
    __nv_bfloat16 *en_h, *en_l, *et_h, *et_l, *sc_h, *sc_l;
    cudaGetSymbolAddress((void**)&e_h, s_emb_h);   cudaGetSymbolAddress((void**)&e_l, s_emb_l);
    cudaGetSymbolAddress((void**)&wi_h, s_wih_h);  cudaGetSymbolAddress((void**)&wi_l, s_wih_l);
    cudaGetSymbolAddress((void**)&c_h, s_cat_h);   cudaGetSymbolAddress((void**)&c_l, s_cat_l);
    cudaGetSymbolAddress((void**)&wo_h, s_wout_h); cudaGetSymbolAddress((void**)&wo_l, s_wout_l);
    cudaGetSymbolAddress((void**)&en_h, s_enc_h);  cudaGetSymbolAddress((void**)&en_l, s_enc_l);
    cudaGetSymbolAddress((void**)&et_h, s_encT_h); cudaGetSymbolAddress((void**)&et_l, s_encT_l);
    cudaGetSymbolAddress((void**)&sc_h, s_sc_h);   cudaGetSymbolAddress((void**)&sc_l, s_sc_l);

    cudaFuncSetAttribute(gemmb, cudaFuncAttributeMaxDynamicSharedMemorySize, 2 * STG_B);
    cudaFuncSetAttribute(lstm_kernel, cudaFuncAttributeMaxDynamicSharedMemorySize, 49152);

    k_prep<<<32, 256>>>(bih, bhh);
    k_transpose<<<dim3(16, 64, 1), dim3(32, 8)>>>(Whh, p_whhT, 2048, 512);
    k_gather<<<512, 256>>>(y, tab);

    k_split<<<512, 256>>>((const float4*)p_emb, (__nv_bfloat162*)e_h, (__nv_bfloat162*)e_l, 131072);
    k_split<<<512, 256>>>((const float4*)Wih, (__nv_bfloat162*)wi_h, (__nv_bfloat162*)wi_l, 131072);
    k_split<<<32000, 256>>>((const float4*)Wout, (__nv_bfloat162*)wo_h, (__nv_bfloat162*)wo_l, 8192000);

    // xw = emb @ W_ih^T + (b_ih + b_hh)
    gemmb<<<dim3(16, 16, 1), 256, 2 * STG_B>>>(e_h, e_l, wi_h, wi_l, p_xw, p_bcomb,
                                               256, 256, 256, 2048, 0, 0, 0, 1.f);

    k_transpose<<<dim3(16, 4, 16), dim3(32, 8)>>>(enc, p_encT, 128, 512);
    k_split<<<1024, 256>>>((const float4*)enc, (__nv_bfloat162*)en_h, (__nv_bfloat162*)en_l, 262144);
    k_split<<<1024, 256>>>((const float4*)p_encT, (__nv_bfloat162*)et_h, (__nv_bfloat162*)et_l, 262144);

    lstm_kernel<<<128, 256, 49152>>>(p_xw);

    k_split<<<2048, 256>>>((const float4*)p_cat, (__nv_bfloat162*)c_h, (__nv_bfloat162*)c_l, 524288);

    // scores = dec @ enc^T / sqrt(H)
    gemmb<<<dim3(1, 1, 16), 256, 2 * STG_B>>>(c_h, c_l, en_h, en_l, p_scores, nullptr,
                                              512, 1024, 512, 128,
                                              131072LL, 65536LL, 16384LL,
                                              0.044194173824159216f);
    k_softmax<<<256, 256>>>(mask);
    k_split<<<256, 256>>>((const float4*)p_scores, (__nv_bfloat162*)sc_h, (__nv_bfloat162*)sc_l, 65536);

    // context = probs @ enc (B = encT [H,L])
    gemmb<<<dim3(1, 4, 16), 256, 2 * STG_B>>>(sc_h, sc_l, et_h, et_l, p_cat + 512, nullptr,
                                              128, 128, 128, 1024,
                                              16384LL, 65536LL, 131072LL, 1.f);

    k_split<<<2048, 256>>>((const float4*)p_cat, (__nv_bfloat162*)c_h, (__nv_bfloat162*)c_l, 524288);

    // logits = cat @ W_out^T + b_out
    gemmb<<<dim3(16, 250, 1), 256, 2 * STG_B>>>(c_h, c_l, wo_h, wo_l, out, bout,
                                                1024, 1024, 1024, 32000, 0, 0, 0, 1.f);
}

// round 7
// speedup vs baseline: 2.1547x; 1.1631x over previous
#include <cuda_runtime.h>
#include <cuda_bf16.h>
#include <cstdint>

// ===================== device scratch (static, no allocation) =====================
__device__ __align__(16) float g_emb[2048 * 256];
__device__ __align__(16) float g_xw[2048 * 2048];
__device__ __align__(16) float g_cat[2048 * 1024];
__device__ __align__(16) float g_scores[16 * 128 * 128];
__device__ __align__(16) float g_encT[16 * 512 * 128];
__device__ __align__(16) float g_whhT[512 * 2048];
__device__ __align__(16) float g_hbuf[512 * 16];
__device__ __align__(16) float g_bcomb[2048];
__device__ unsigned g_bar;
__device__ unsigned g_sense;

__device__ __align__(16) __nv_bfloat16 s_emb_h[2048 * 256],  s_emb_l[2048 * 256];
__device__ __align__(16) __nv_bfloat16 s_wih_h[2048 * 256],  s_wih_l[2048 * 256];
__device__ __align__(16) __nv_bfloat16 s_cat_h[2048 * 1024], s_cat_l[2048 * 1024];
__device__ __align__(16) __nv_bfloat16 s_wout_h[32000 * 1024], s_wout_l[32000 * 1024];
__device__ __align__(16) __nv_bfloat16 s_enc_h[16 * 128 * 512], s_enc_l[16 * 128 * 512];
__device__ __align__(16) __nv_bfloat16 s_encT_h[16 * 512 * 128], s_encT_l[16 * 512 * 128];
__device__ __align__(16) __nv_bfloat16 s_sc_h[16 * 128 * 128], s_sc_l[16 * 128 * 128];

// ===================== helpers =====================
__device__ __forceinline__ float sigm(float x) { return 1.f / (1.f + expf(-x)); }

__device__ __forceinline__ void mma16(float* d, const uint32_t* a, const uint32_t* b) {
    asm volatile(
        "mma.sync.aligned.m16n8k16.row.col.f32.bf16.bf16.f32 "
        "{%0,%1,%2,%3}, {%4,%5,%6,%7}, {%8,%9}, {%0,%1,%2,%3};"
        : "+f"(d[0]), "+f"(d[1]), "+f"(d[2]), "+f"(d[3])
        : "r"(a[0]), "r"(a[1]), "r"(a[2]), "r"(a[3]), "r"(b[0]), "r"(b[1]));
}

__device__ __forceinline__ void ldsm4(uint32_t& r0, uint32_t& r1, uint32_t& r2, uint32_t& r3,
                                      uint32_t addr) {
    asm volatile("ldmatrix.sync.aligned.m8n8.x4.shared.b16 {%0,%1,%2,%3}, [%4];"
                 : "=r"(r0), "=r"(r1), "=r"(r2), "=r"(r3) : "r"(addr));
}

__device__ __forceinline__ void cpasync16(uint32_t dst, const void* src) {
    asm volatile("cp.async.cg.shared.global [%0], [%1], 16;" :: "r"(dst), "l"(src));
}

// ===================== gemmo: big-GEMM kernel (256x128 tile, 3-stage, 1 sync/kt) ====
// C[m,n] = alpha*sum_k A[m,k]B[n,k] + bias[n]; A,B pre-split bf16 hi/lo, k-major.
// 512 threads = 16 warps (4x4), warp tile 64x32. K % 32 == 0.
#define OPITCH 80
#define OA_B (256 * OPITCH)             // 20480 B per A matrix (hi or lo)
#define OB_B (128 * OPITCH)             // 10240 B per B matrix
#define OSTG (2 * OA_B + 2 * OB_B)      // 61440 B per stage
#define OSMEM (3 * OSTG)                // 184320 B

__global__ void __launch_bounds__(512, 1) gemmo(
    const __nv_bfloat16* __restrict__ Ahg, const __nv_bfloat16* __restrict__ Alg,
    const __nv_bfloat16* __restrict__ Bhg, const __nv_bfloat16* __restrict__ Blg,
    float* __restrict__ C, const float* __restrict__ bias,
    int K, int lda, int ldb, int ldc, float alpha)
{
    extern __shared__ char smc[];
    const uint32_t sb = (uint32_t)__cvta_generic_to_shared(smc);

    const int m0 = blockIdx.x * 256, n0 = blockIdx.y * 128;
    const int tid = threadIdx.x, lane = tid & 31, warp = tid >> 5;
    const int wm = (warp & 3) * 64, wn = (warp >> 2) * 32;
    const int gid = lane >> 2, tig = lane & 3;
    const int rsel = lane & 15, csel = (lane >> 4) * 16;
    const int KT = K >> 5;

    // load mapping: A chunks 1024 (2/thread), B chunks 512 (1/thread)
    const int ar0 = tid >> 1;                 // A chunk i=0 row: c = tid -> row c>>2? use c = tid*2..
    const int brow = tid >> 2, boff = tid & 3;

    float acc[4][4][4];
#pragma unroll
    for (int a = 0; a < 4; a++)
#pragma unroll
        for (int b = 0; b < 4; b++)
#pragma unroll
            for (int d = 0; d < 4; d++) acc[a][b][d] = 0.f;

#define OLOAD(KT_IDX, ST)                                                                 \
    {                                                                                     \
        const int kof = (KT_IDX) * 32;                                                    \
        const uint32_t st = sb + (ST) * OSTG;                                             \
        _Pragma("unroll")                                                                 \
        for (int i = 0; i < 2; i++) {                                                     \
            const int c = tid + 512 * i;                                                  \
            const int arow = c >> 2, aoff = c & 3;                                        \
            const uint32_t ad = st + arow * OPITCH + aoff * 16;                           \
            cpasync16(ad,        Ahg + (long long)(m0 + arow) * lda + kof + aoff * 8);    \
            cpasync16(ad + OA_B, Alg + (long long)(m0 + arow) * lda + kof + aoff * 8);    \
        }                                                                                 \
        const uint32_t bd = st + 2 * OA_B + brow * OPITCH + boff * 16;                    \
        cpasync16(bd,        Bhg + (long long)(n0 + brow) * ldb + kof + boff * 8);        \
        cpasync16(bd + OB_B, Blg + (long long)(n0 + brow) * ldb + kof + boff * 8);        \
        asm volatile("cp.async.commit_group;");                                           \
    }

    OLOAD(0, 0);
    OLOAD(1, 1);

    for (int kt = 0; kt < KT; kt++) {
        if (kt + 2 < KT) asm volatile("cp.async.wait_group 1;");
        else             asm volatile("cp.async.wait_group 0;");
        __syncthreads();
        if (kt + 2 < KT) OLOAD(kt + 2, (kt + 2) % 3);

        const uint32_t base = sb + (kt % 3) * OSTG;
#pragma unroll
        for (int k16 = 0; k16 < 2; k16++) {
            const uint32_t kof = k16 * 32 + csel;
            uint32_t ah[4][4], al[4][4], bh[4][2], bl[4][2];
#pragma unroll
            for (int mf = 0; mf < 4; mf++) {
                const uint32_t ra = base + (wm + mf * 16 + rsel) * OPITCH + kof;
                ldsm4(ah[mf][0], ah[mf][1], ah[mf][2], ah[mf][3], ra);
                ldsm4(al[mf][0], al[mf][1], al[mf][2], al[mf][3], ra + OA_B);
            }
#pragma unroll
            for (int np = 0; np < 2; np++) {
                const uint32_t rb = base + 2 * OA_B + (wn + np * 16 + rsel) * OPITCH + kof;
                uint32_t t0, t1, t2, t3;
                ldsm4(t0, t1, t2, t3, rb);
                bh[2 * np][0] = t0; bh[2 * np][1] = t2;
                bh[2 * np + 1][0] = t1; bh[2 * np + 1][1] = t3;
                ldsm4(t0, t1, t2, t3, rb + OB_B);
                bl[2 * np][0] = t0; bl[2 * np][1] = t2;
                bl[2 * np + 1][0] = t1; bl[2 * np + 1][1] = t3;
            }
#pragma unroll
            for (int mf = 0; mf < 4; mf++)
#pragma unroll
                for (int nf = 0; nf < 4; nf++) {
                    mma16(acc[mf][nf], ah[mf], bh[nf]);
                    mma16(acc[mf][nf], ah[mf], bl[nf]);
                    mma16(acc[mf][nf], al[mf], bh[nf]);
                }
        }
    }

#pragma unroll
    for (int mf = 0; mf < 4; mf++) {
        const int r = m0 + wm + mf * 16 + gid;
#pragma unroll
        for (int nf = 0; nf < 4; nf++) {
            const int c = n0 + wn + nf * 8 + 2 * tig;
            float b0 = bias ? bias[c] : 0.f;
            float b1 = bias ? bias[c + 1] : 0.f;
            float2 v0 = {alpha * acc[mf][nf][0] + b0, alpha * acc[mf][nf][1] + b1};
            float2 v1 = {alpha * acc[mf][nf][2] + b0, alpha * acc[mf][nf][3] + b1};
            *(float2*)&C[(long long)r * ldc + c] = v0;
            *(float2*)&C[(long long)(r + 8) * ldc + c] = v1;
        }
    }
}

// ===================== gemmb: 128x128 tile (small/batched GEMMs, unchanged from R5) =====
#define PITCH 80
#define MAT_B (128 * PITCH)
#define STG_B (4 * MAT_B)

__global__ void __launch_bounds__(256, 2) gemmb(
    const __nv_bfloat16* __restrict__ Ahg, const __nv_bfloat16* __restrict__ Alg,
    const __nv_bfloat16* __restrict__ Bhg, const __nv_bfloat16* __restrict__ Blg,
    float* __restrict__ C, const float* __restrict__ bias,
    int K, int lda, int ldb, int ldc,
    long long sA, long long sB, long long sC, float alpha)
{
    extern __shared__ char smc[];
    const uint32_t sb = (uint32_t)__cvta_generic_to_shared(smc);

    Ahg += sA * blockIdx.z; Alg += sA * blockIdx.z;
    Bhg += sB * blockIdx.z; Blg += sB * blockIdx.z;
    C += sC * blockIdx.z;

    const int m0 = blockIdx.x * 128, n0 = blockIdx.y * 128;
    const int tid = threadIdx.x, lane = tid & 31, warp = tid >> 5;
    const int wm = (warp & 1) * 64, wn = (warp >> 1) * 32;
    const int gid = lane >> 2, tig = lane & 3;
    const int rsel = lane & 15, csel = (lane >> 4) * 16;
    const int KT = K >> 5;
    const int lrow = tid >> 2, loff = tid & 3;

    float acc[4][4][4];
#pragma unroll
    for (int a = 0; a < 4; a++)
#pragma unroll
        for (int b = 0; b < 4; b++)
#pragma unroll
            for (int d = 0; d < 4; d++) acc[a][b][d] = 0.f;

#define LOAD_STAGE(KT_IDX, ST)                                                          \
    {                                                                                   \
        const int kofs = (KT_IDX) * 32 + loff * 8;                                      \
        const uint32_t db = sb + (ST) * STG_B + lrow * PITCH + loff * 16;               \
        cpasync16(db,                  Ahg + (long long)(m0 + lrow) * lda + kofs);      \
        cpasync16(db + 64 * PITCH,     Ahg + (long long)(m0 + lrow + 64) * lda + kofs); \
        cpasync16(db + MAT_B,          Alg + (long long)(m0 + lrow) * lda + kofs);      \
        cpasync16(db + MAT_B + 64 * PITCH, Alg + (long long)(m0 + lrow + 64) * lda + kofs); \
        cpasync16(db + 2 * MAT_B,      Bhg + (long long)(n0 + lrow) * ldb + kofs);      \
        cpasync16(db + 2 * MAT_B + 64 * PITCH, Bhg + (long long)(n0 + lrow + 64) * ldb + kofs); \
        cpasync16(db + 3 * MAT_B,      Blg + (long long)(n0 + lrow) * ldb + kofs);      \
        cpasync16(db + 3 * MAT_B + 64 * PITCH, Blg + (long long)(n0 + lrow + 64) * ldb + kofs); \
        asm volatile("cp.async.commit_group;");                                         \
    }

    LOAD_STAGE(0, 0);

    for (int kt = 0; kt < KT; kt++) {
        if (kt + 1 < KT) {
            LOAD_STAGE(kt + 1, (kt + 1) & 1);
            asm volatile("cp.async.wait_group 1;");
        } else {
            asm volatile("cp.async.wait_group 0;");
        }
        __syncthreads();

        const uint32_t base = sb + (kt & 1) * STG_B;
#pragma unroll
        for (int k16 = 0; k16 < 2; k16++) {
            const uint32_t kof = k16 * 32 + csel;
            uint32_t ah[4][4], al[4][4], bh[4][2], bl[4][2];
#pragma unroll
            for (int mf = 0; mf < 4; mf++) {
                const uint32_t ra = base + (wm + mf * 16 + rsel) * PITCH + kof;
                ldsm4(ah[mf][0], ah[mf][1], ah[mf][2], ah[mf][3], ra);
                ldsm4(al[mf][0], al[mf][1], al[mf][2], al[mf][3], ra + MAT_B);
            }
#pragma unroll
            for (int np = 0; np < 2; np++) {
                const uint32_t rb = base + 2 * MAT_B + (wn + np * 16 + rsel) * PITCH + kof;
                uint32_t t0, t1, t2, t3;
                ldsm4(t0, t1, t2, t3, rb);
                bh[2 * np][0] = t0; bh[2 * np][1] = t2;
                bh[2 * np + 1][0] = t1; bh[2 * np + 1][1] = t3;
                ldsm4(t0, t1, t2, t3, rb + MAT_B);
                bl[2 * np][0] = t0; bl[2 * np][1] = t2;
                bl[2 * np + 1][0] = t1; bl[2 * np + 1][1] = t3;
            }
#pragma unroll
            for (int mf = 0; mf < 4; mf++)
#pragma unroll
                for (int nf = 0; nf < 4; nf++) {
                    mma16(acc[mf][nf], ah[mf], bh[nf]);
                    mma16(acc[mf][nf], ah[mf], bl[nf]);
                    mma16(acc[mf][nf], al[mf], bh[nf]);
                }
        }
        __syncthreads();
    }

#pragma unroll
    for (int mf = 0; mf < 4; mf++) {
        const int r = m0 + wm + mf * 16 + gid;
#pragma unroll
        for (int nf = 0; nf < 4; nf++) {
            const int c = n0 + wn + nf * 8 + 2 * tig;
            float b0 = bias ? bias[c] : 0.f;
            float b1 = bias ? bias[c + 1] : 0.f;
            float2 v0 = {alpha * acc[mf][nf][0] + b0, alpha * acc[mf][nf][1] + b1};
            float2 v1 = {alpha * acc[mf][nf][2] + b0, alpha * acc[mf][nf][3] + b1};
            *(float2*)&C[(long long)r * ldc + c] = v0;
            *(float2*)&C[(long long)(r + 8) * ldc + c] = v1;
        }
    }
}

// ===================== split kernel =====================
__global__ void k_split(const float4* __restrict__ in, __nv_bfloat162* __restrict__ hi,
                        __nv_bfloat162* __restrict__ lo, int n4) {
    int i = blockIdx.x * 256 + threadIdx.x;
    if (i >= n4) return;
    float4 v = in[i];
    __nv_bfloat16 h0 = __float2bfloat16(v.x), h1 = __float2bfloat16(v.y);
    __nv_bfloat16 h2 = __float2bfloat16(v.z), h3 = __float2bfloat16(v.w);
    hi[2 * i]     = __nv_bfloat162(h0, h1);
    hi[2 * i + 1] = __nv_bfloat162(h2, h3);
    lo[2 * i]     = __nv_bfloat162(__float2bfloat16(v.x - __bfloat162float(h0)),
                                   __float2bfloat16(v.y - __bfloat162float(h1)));
    lo[2 * i + 1] = __nv_bfloat162(__float2bfloat16(v.z - __bfloat162float(h2)),
                                   __float2bfloat16(v.w - __bfloat162float(h3)));
}

// ===================== small kernels =====================
__global__ void k_prep(const float* __restrict__ bih, const float* __restrict__ bhh) {
    int i = blockIdx.x * 256 + threadIdx.x;
    if (i < 2048) g_bcomb[i] = bih[i] + bhh[i];
    if (i < 8192) g_hbuf[i] = 0.f;
    if (i == 0) { g_bar = 0; g_sense = 0; }
}

__global__ void k_gather(const int* __restrict__ y, const float* __restrict__ tab) {
    int i = blockIdx.x * 256 + threadIdx.x;
    if (i < 2048 * 64) {
        int bs = i >> 6, e = i & 63;
        ((float4*)g_emb)[i] = ((const float4*)(tab + (long long)y[bs] * 256))[e];
    }
}

__global__ void k_transpose(const float* __restrict__ in, float* __restrict__ out, int R, int C) {
    __shared__ float t[32][33];
    in += (long long)blockIdx.z * R * C;
    out += (long long)blockIdx.z * R * C;
    int c0 = blockIdx.x * 32, r0 = blockIdx.y * 32;
    int x = threadIdx.x, y = threadIdx.y;
#pragma unroll
    for (int i = 0; i < 32; i += 8)
        if (r0 + y + i < R && c0 + x < C) t[y + i][x] = in[(r0 + y + i) * C + c0 + x];
    __syncthreads();
#pragma unroll
    for (int i = 0; i < 32; i += 8)
        if (c0 + y + i < C && r0 + x < R) out[(c0 + y + i) * R + r0 + x] = t[x][y + i];
}

__global__ void k_softmax(const uint32_t* __restrict__ mask) {
    int w = (blockIdx.x * blockDim.x + threadIdx.x) >> 5;
    int lane = threadIdx.x & 31;
    if (w >= 2048) return;
    int b = w >> 7;
    float* row = g_scores + w * 128;
    const uint32_t* m = mask + b * 128;
    float v[4];
    float mx = -1e30f;
#pragma unroll
    for (int i = 0; i < 4; i++) {
        int l = lane + 32 * i;
        v[i] = (m[l] != 0u) ? row[l] : -1e9f;
        mx = fmaxf(mx, v[i]);
    }
#pragma unroll
    for (int o = 16; o > 0; o >>= 1) mx = fmaxf(mx, __shfl_xor_sync(0xffffffffu, mx, o));
    float s = 0.f;
#pragma unroll
    for (int i = 0; i < 4; i++) { v[i] = expf(v[i] - mx); s += v[i]; }
#pragma unroll
    for (int o = 16; o > 0; o >>= 1) s += __shfl_xor_sync(0xffffffffu, s, o);
    float inv = 1.f / s;
#pragma unroll
    for (int i = 0; i < 4; i++) row[lane + 32 * i] = v[i] * inv;
}

// ===================== persistent LSTM — ONE grid barrier per step =====================
// Block bk owns units u0=bk*4..bk*4+3: computes gate rows {g*512+u0+uu} for all b,
// then the cell update locally (smem), one gridbar per step.
__device__ __forceinline__ void gridbar(unsigned target) {
    __syncthreads();
    if (threadIdx.x == 0) {
        __threadfence();
        unsigned v = atomicAdd(&g_bar, 1);
        if (v == 127u) {
            g_bar = 0;
            __threadfence();
            atomicAdd(&g_sense, 1);
        }
        while (*(volatile unsigned*)&g_sense < target) __nanosleep(64);
        __threadfence();
    }
    __syncthreads();
}

__global__ void __launch_bounds__(256) lstm_kernel(const float* __restrict__ xw) {
    extern __shared__ float smf[];
    float* h_sm = smf;              // [512][16]
    float* red = smf + 8192;        // [16ks][16j][16b]
    float* sgate = smf + 8192 + 4096;  // [16j][16b]

    const int tid = threadIdx.x, bk = blockIdx.x;
    const int ks = tid >> 4;
    const int bg = (tid >> 2) & 3;
    const int jg = tid & 3;                 // gate index g
    const int u0 = bk * 4;
    const int b0 = bg * 4;
    const int rj = tid >> 4, rb = tid & 15;

    // phase-2 owner: threads 0..63 -> (uu, b)
    const int puu = tid >> 4, pbb = tid & 15;
    float creg = 0.f;

    for (int t = 0; t < 128; t++) {
#pragma unroll
        for (int i = tid; i < 8192; i += 256) h_sm[i] = g_hbuf[i];
        __syncthreads();

        float a[4][4];
#pragma unroll
        for (int jj = 0; jj < 4; jj++)
#pragma unroll
            for (int bb = 0; bb < 4; bb++) a[jj][bb] = 0.f;

        const float* wp = g_whhT + (ks * 32) * 2048 + jg * 512 + u0;
        const float* hp = h_sm + (ks * 32) * 16 + b0;
#pragma unroll 8
        for (int k = 0; k < 32; k++) {
            float4 wv = *(const float4*)wp;
            float4 hv = *(const float4*)hp;
            wp += 2048; hp += 16;
            float wa[4] = {wv.x, wv.y, wv.z, wv.w};
            float ha[4] = {hv.x, hv.y, hv.z, hv.w};
#pragma unroll
            for (int jj = 0; jj < 4; jj++)
#pragma unroll
                for (int bb = 0; bb < 4; bb++) a[jj][bb] = fmaf(wa[jj], ha[bb], a[jj][bb]);
        }
#pragma unroll
        for (int jj = 0; jj < 4; jj++)
#pragma unroll
            for (int bb = 0; bb < 4; bb++)
                red[ks * 256 + (jg * 4 + jj) * 16 + (bg * 4 + bb)] = a[jj][bb];
        __syncthreads();

        // k-reduce: j_local = rj = g*4+uu, b = rb
        float s = 0.f;
#pragma unroll
        for (int q = 0; q < 16; q++) s += red[q * 256 + rj * 16 + rb];
        const int g = rj >> 2, uu = rj & 3;
        s += xw[(rb * 128 + t) * 2048 + g * 512 + u0 + uu];
        sgate[rj * 16 + rb] = s;
        __syncthreads();

        // block-local cell update (threads 0..63)
        if (tid < 64) {
            float gi = sgate[(0 * 4 + puu) * 16 + pbb];
            float gf = sgate[(1 * 4 + puu) * 16 + pbb];
            float gg = sgate[(2 * 4 + puu) * 16 + pbb];
            float go = sgate[(3 * 4 + puu) * 16 + pbb];
            creg = sigm(gf) * creg + sigm(gi) * tanhf(gg);
            float h = sigm(go) * tanhf(creg);
            g_hbuf[(u0 + puu) * 16 + pbb] = h;
            g_cat[(pbb * 128 + t) * 1024 + u0 + puu] = h;
        }
        gridbar(t + 1);
    }
}

// ===================== host launcher =====================
extern "C" void kernel_launch(void* const* d_in, const int* in_sizes, int n_in,
                              void* d_out, int out_size) {
    const int* y = (const int*)d_in[0];
    const float* tab = (const float*)d_in[1];
    const float* Wih = (const float*)d_in[2];
    const float* Whh = (const float*)d_in[3];
    const float* bih = (const float*)d_in[4];
    const float* bhh = (const float*)d_in[5];
    const float* enc = (const float*)d_in[6];
    const uint32_t* mask = (const uint32_t*)d_in[7];
    const float* Wout = (const float*)d_in[8];
    const float* bout = (const float*)d_in[9];
    float* out = (float*)d_out;

    float *p_emb, *p_xw, *p_cat, *p_scores, *p_encT, *p_whhT, *p_bcomb;
    cudaGetSymbolAddress((void**)&p_emb, g_emb);
    cudaGetSymbolAddress((void**)&p_xw, g_xw);
    cudaGetSymbolAddress((void**)&p_cat, g_cat);
    cudaGetSymbolAddress((void**)&p_scores, g_scores);
    cudaGetSymbolAddress((void**)&p_encT, g_encT);
    cudaGetSymbolAddress((void**)&p_whhT, g_whhT);
    cudaGetSymbolAddress((void**)&p_bcomb, g_bcomb);

    __nv_bfloat16 *e_h, *e_l, *wi_h, *wi_l, *c_h, *c_l, *wo_h, *wo_l;
    __nv_bfloat16 *en_h, *en_l, *et_h, *et_l, *sc_h, *sc_l;
    cudaGetSymbolAddress((void**)&e_h, s_emb_h);   cudaGetSymbolAddress((void**)&e_l, s_emb_l);
    cudaGetSymbolAddress((void**)&wi_h, s_wih_h);  cudaGetSymbolAddress((void**)&wi_l, s_wih_l);
    cudaGetSymbolAddress((void**)&c_h, s_cat_h);   cudaGetSymbolAddress((void**)&c_l, s_cat_l);
    cudaGetSymbolAddress((void**)&wo_h, s_wout_h); cudaGetSymbolAddress((void**)&wo_l, s_wout_l);
    cudaGetSymbolAddress((void**)&en_h, s_enc_h);  cudaGetSymbolAddress((void**)&en_l, s_enc_l);
    cudaGetSymbolAddress((void**)&et_h, s_encT_h); cudaGetSymbolAddress((void**)&et_l, s_encT_l);
    cudaGetSymbolAddress((void**)&sc_h, s_sc_h);   cudaGetSymbolAddress((void**)&sc_l, s_sc_l);

    cudaFuncSetAttribute(gemmb, cudaFuncAttributeMaxDynamicSharedMemorySize, 2 * STG_B);
    cudaFuncSetAttribute(gemmo, cudaFuncAttributeMaxDynamicSharedMemorySize, OSMEM);
    cudaFuncSetAttribute(lstm_kernel, cudaFuncAttributeMaxDynamicSharedMemorySize, 53248);

    k_prep<<<32, 256>>>(bih, bhh);
    k_transpose<<<dim3(16, 64, 1), dim3(32, 8)>>>(Whh, p_whhT, 2048, 512);
    k_gather<<<512, 256>>>(y, tab);

    k_split<<<512, 256>>>((const float4*)p_emb, (__nv_bfloat162*)e_h, (__nv_bfloat162*)e_l, 131072);
    k_split<<<512, 256>>>((const float4*)Wih, (__nv_bfloat162*)wi_h, (__nv_bfloat162*)wi_l, 131072);
    k_split<<<32000, 256>>>((const float4*)Wout, (__nv_bfloat162*)wo_h, (__nv_bfloat162*)wo_l, 8192000);

    // xw = emb @ W_ih^T + (b_ih + b_hh)   [M=2048, N=2048, K=256]
    gemmo<<<dim3(8, 16), 512, OSMEM>>>(e_h, e_l, wi_h, wi_l, p_xw, p_bcomb,
                                       256, 256, 256, 2048, 1.f);

    k_transpose<<<dim3(16, 4, 16), dim3(32, 8)>>>(enc, p_encT, 128, 512);
    k_split<<<1024, 256>>>((const float4*)enc, (__nv_bfloat162*)en_h, (__nv_bfloat162*)en_l, 262144);
    k_split<<<1024, 256>>>((const float4*)p_encT, (__nv_bfloat162*)et_h, (__nv_bfloat162*)et_l, 262144);

    lstm_kernel<<<128, 256, 53248>>>(p_xw);

    k_split<<<2048, 256>>>((const float4*)p_cat, (__nv_bfloat162*)c_h, (__nv_bfloat162*)c_l, 524288);

    // scores = dec @ enc^T / sqrt(H)
    gemmb<<<dim3(1, 1, 16), 256, 2 * STG_B>>>(c_h, c_l, en_h, en_l, p_scores, nullptr,
                                              512, 1024, 512, 128,
                                              131072LL, 65536LL, 16384LL,
                                              0.044194173824159216f);
    k_softmax<<<256, 256>>>(mask);
    k_split<<<256, 256>>>((const float4*)p_scores, (__nv_bfloat162*)sc_h, (__nv_bfloat162*)sc_l, 65536);

    // context = probs @ enc (B = encT [H,L])
    gemmb<<<dim3(1, 4, 16), 256, 2 * STG_B>>>(sc_h, sc_l, et_h, et_l, p_cat + 512, nullptr,
                                              128, 128, 128, 1024,
                                              16384LL, 65536LL, 131072LL, 1.f);

    k_split<<<2048, 256>>>((const float4*)p_cat, (__nv_bfloat162*)c_h, (__nv_bfloat162*)c_l, 524288);

    // logits = cat @ W_out^T + b_out   [M=2048, N=32000, K=1024]
    gemmo<<<dim3(8, 250), 512, OSMEM>>>(c_h, c_l, wo_h, wo_l, out, bout,
                                        1024, 1024, 1024, 32000, 1.f);
}